// round 8
// baseline (speedup 1.0000x reference)
#include <cuda_runtime.h>

// ProbAttention (Informer ProbSparse) for B=2, L=4096, H=8, D=64, sample_k = n_top = 45.

#define Bb   2
#define Ll   4096
#define Hh   8
#define Dd   64
#define SSK  45          // sample_k == n_top
#define BH   (Bb*Hh)     // 16
#define NC   16          // kv chunks in phase 3
#define CK   256         // keys per chunk (NC*CK == Ll)
#define SST  257         // padded ss row stride (floats)

typedef unsigned long long ull;

// ---- scratch (static device globals: no allocation allowed) ----
__device__ int    g_idx_is64;
__device__ float  g_M[BH * Ll];
__device__ int    g_top[BH * SSK];
__device__ float  g_pmax[BH * NC * SSK];
__device__ float  g_psum[BH * NC * SSK];
__device__ float4 g_pout[BH * NC * SSK * (Dd / 4)];

// ---- f32x2 packed-FMA helpers ----
__device__ __forceinline__ ull fma2(ull a, ull b, ull c) {
    ull d;
    asm("fma.rn.f32x2 %0, %1, %2, %3;" : "=l"(d) : "l"(a), "l"(b), "l"(c));
    return d;
}
__device__ __forceinline__ ull pack2(float x, float y) {
    ull r;
    asm("mov.b64 %0, {%1, %2};" : "=l"(r) : "f"(x), "f"(y));
    return r;
}
__device__ __forceinline__ void unpack2(ull v, float& x, float& y) {
    asm("mov.b64 {%0, %1}, %2;" : "=f"(x), "=f"(y) : "l"(v));
}

// ---------------- K0: zero output + detect index dtype ----------------
// Block 0 also detects int32 vs int64: indices are < 4096, so if the buffer is
// int64 every odd 32-bit word is 0; int32 makes that astronomically unlikely.
__global__ void k0_zero(float4* __restrict__ out4, int n4,
                        const unsigned* __restrict__ idxsrc) {
    if (blockIdx.x == 0) {
        __shared__ int nz;
        if (threadIdx.x == 0) nz = 0;
        __syncthreads();
        if (threadIdx.x < 128) {
            unsigned v = idxsrc[threadIdx.x * 2 + 1];
            if (v != 0u) atomicAdd(&nz, 1);
        }
        __syncthreads();
        if (threadIdx.x == 0) g_idx_is64 = (nz == 0) ? 1 : 0;
    }
    int i = blockIdx.x * 256 + threadIdx.x;
    if (i < n4) out4[i] = make_float4(0.f, 0.f, 0.f, 0.f);
}

// ---------------- K1: sampled scores M ----------------
// One warp per (b,l). Coalesced: LDG t reads float4 index (32t + lane) -> 512B
// contiguous per LDG. Chunk 32t+lane belongs to head h = 2t + (lane>>4);
// reduce over the 16-lane half with 4 shfl_xor. Indices read directly from the
// input buffer (uniform per warp, L2-resident), dtype branch hoisted.
__global__ __launch_bounds__(256) void k1_score(const float4* __restrict__ q4,
                                                const float4* __restrict__ k4,
                                                const void* __restrict__ idxsrc) {
    int w    = blockIdx.x * 8 + (threadIdx.x >> 5);
    int lane = threadIdx.x & 31;
    int b = w >> 12;
    int l = w & (Ll - 1);

    const float4* qp = q4 + (size_t)(b * Ll + l) * (Hh * Dd / 4);
    float4 qv[4];
    #pragma unroll
    for (int t = 0; t < 4; t++) qv[t] = qp[t * 32 + lane];

    float mx[4] = {-1e30f, -1e30f, -1e30f, -1e30f};
    float sm[4] = {0.f, 0.f, 0.f, 0.f};

    const int is64 = g_idx_is64;
    const long long* ip64 = (const long long*)idxsrc + (size_t)l * SSK;
    const int*       ip32 = (const int*)idxsrc + (size_t)l * SSK;

    #pragma unroll 2
    for (int s = 0; s < SSK; s++) {
        int idx = is64 ? (int)ip64[s] : ip32[s];
        const float4* kp = k4 + (size_t)(b * Ll + idx) * (Hh * Dd / 4);
        #pragma unroll
        for (int t = 0; t < 4; t++) {
            float4 kv = kp[t * 32 + lane];
            float p = qv[t].x*kv.x + qv[t].y*kv.y + qv[t].z*kv.z + qv[t].w*kv.w;
            p += __shfl_xor_sync(0xffffffffu, p, 8);
            p += __shfl_xor_sync(0xffffffffu, p, 4);
            p += __shfl_xor_sync(0xffffffffu, p, 2);
            p += __shfl_xor_sync(0xffffffffu, p, 1);
            mx[t] = fmaxf(mx[t], p);
            sm[t] += p;
        }
    }
    if ((lane & 15) == 0) {
        int half = lane >> 4;
        #pragma unroll
        for (int t = 0; t < 4; t++) {
            int h = 2 * t + half;
            g_M[(b * Hh + h) * Ll + l] = mx[t] - sm[t] * (1.0f / (float)Ll);
        }
    }
}

// ---------------- K2: top-45 per (b,h) via 4-round radix select ----------------
__global__ __launch_bounds__(256) void k2_topk() {
    int bh  = blockIdx.x;
    int tid = threadIdx.x;
    int wid = tid >> 5, lane = tid & 31;

    __shared__ unsigned hist[256];
    __shared__ unsigned warptot[8];
    __shared__ unsigned sh_pivot, sh_above;
    __shared__ int n_gt, n_eq;

    unsigned key[16];
    #pragma unroll
    for (int i = 0; i < 16; i++) {
        unsigned u = __float_as_uint(g_M[bh * Ll + i * 256 + tid]);
        key[i] = (u & 0x80000000u) ? ~u : (u | 0x80000000u);
    }

    unsigned prefix = 0, pmask = 0;
    int need = SSK;

    #pragma unroll
    for (int round = 0; round < 4; round++) {
        int shift = 24 - round * 8;
        hist[tid] = 0;
        if (tid == 0) { n_gt = 0; n_eq = 0; }
        __syncthreads();
        #pragma unroll
        for (int i = 0; i < 16; i++)
            if ((key[i] & pmask) == prefix)
                atomicAdd(&hist[(key[i] >> shift) & 255u], 1u);
        __syncthreads();

        unsigned x = hist[tid];
        unsigned s = x;
        #pragma unroll
        for (int o = 1; o < 32; o <<= 1) {
            unsigned y = __shfl_down_sync(0xffffffffu, s, o);
            if (lane + o < 32) s += y;
        }
        unsigned wt = __shfl_sync(0xffffffffu, s, 0);
        if (lane == 0) warptot[wid] = wt;
        __syncthreads();
        unsigned hs = 0;
        #pragma unroll
        for (int w2 = 0; w2 < 8; w2++)
            if (w2 > wid) hs += warptot[w2];
        unsigned S = s + hs;
        unsigned above = S - x;
        if ((int)S >= need && (int)above < need) {
            sh_pivot = (unsigned)tid;
            sh_above = above;
        }
        __syncthreads();
        prefix |= sh_pivot << shift;
        pmask  |= 0xffu << shift;
        need   -= (int)sh_above;
        __syncthreads();
    }

    int base = bh * SSK;
    #pragma unroll
    for (int i = 0; i < 16; i++)
        if (key[i] > prefix) {
            int p = atomicAdd(&n_gt, 1);
            g_top[base + p] = i * 256 + tid;
        }
    __syncthreads();
    int gt = n_gt;
    #pragma unroll
    for (int i = 0; i < 16; i++)
        if (key[i] == prefix) {
            int e = atomicAdd(&n_eq, 1);
            if (e < need) g_top[base + gt + e] = i * 256 + tid;
        }
}

// ---------------- K3: split-KV sparse attention partials ----------------
// 512 threads/CTA (16 warps) at unchanged 124KB smem -> same 1 CTA/SM but 2x
// warps for latency hiding; per-thread work halved.
#define K3T  512
#define QS2F (23 * 128)
#define K3_SMEM ((QS2F + CK * Dd + SSK * SST) * 4 + 256)

// One S-phase pass over NI u-pairs starting at pair index I0; j in [0,CK).
template <int NI>
__device__ __forceinline__ void s_pass(int i0, int j, const float4* ks4,
                                       const ulonglong2* qsU, float* ss) {
    ull acc[NI];
    #pragma unroll
    for (int i = 0; i < NI; i++) acc[i] = 0ull;

    #pragma unroll 1
    for (int dc = 0; dc < 16; dc++) {
        float4 kr = ks4[j * 16 + (dc ^ (j & 7))];
        ull kk0 = pack2(kr.x, kr.x);
        ull kk1 = pack2(kr.y, kr.y);
        ull kk2 = pack2(kr.z, kr.z);
        ull kk3 = pack2(kr.w, kr.w);
        #pragma unroll
        for (int i = 0; i < NI; i++) {
            ulonglong2 qA = qsU[(i0 + i) * 32 + dc * 2];      // d = 4dc, 4dc+1
            ulonglong2 qB = qsU[(i0 + i) * 32 + dc * 2 + 1];  // d = 4dc+2, 4dc+3
            acc[i] = fma2(qA.x, kk0, acc[i]);
            acc[i] = fma2(qA.y, kk1, acc[i]);
            acc[i] = fma2(qB.x, kk2, acc[i]);
            acc[i] = fma2(qB.y, kk3, acc[i]);
        }
    }
    #pragma unroll
    for (int i = 0; i < NI; i++) {
        float lo, hi;
        unpack2(acc[i], lo, hi);
        int u = 2 * (i0 + i);
        ss[u * SST + j] = lo;
        if (u + 1 < SSK) ss[(u + 1) * SST + j] = hi;
    }
}

__global__ __launch_bounds__(K3T) void k3_attn(const float4* __restrict__ q4,
                                               const float4* __restrict__ k4g,
                                               const float4* __restrict__ v4g) {
    int c  = blockIdx.x;
    int bh = blockIdx.y;
    int b = bh >> 3, h = bh & 7;
    int tid = threadIdx.x;

    extern __shared__ float smem[];
    float* qs2f = smem;                   // 23*128 floats (u-pair packed Q)
    float* ks   = qs2f + QS2F;            // 16384 floats
    float* ss   = ks + CK * Dd;           // 45*257 floats
    int*   tops = (int*)(ss + SSK * SST);
    float4*           ks4 = (float4*)ks;
    const ulonglong2* ksU = (const ulonglong2*)ks;
    const ulonglong2* qsU = (const ulonglong2*)qs2f;

    if (tid < SSK) tops[tid] = g_top[bh * SSK + tid];
    __syncthreads();

    // stage Q in u-pair-packed layout: qs2f[(u>>1)*128 + 2d + (u&1)] = q[u][d]
    for (int i = tid; i < 46 * 16; i += K3T) {
        int u = i >> 4, c4 = i & 15;
        float4 qv = (u < SSK)
            ? q4[((size_t)(b * Ll + tops[u]) * Hh + h) * (Dd / 4) + c4]
            : make_float4(0.f, 0.f, 0.f, 0.f);
        float* dst = qs2f + ((u >> 1) * 128 + 8 * c4) + (u & 1);
        dst[0] = qv.x; dst[2] = qv.y; dst[4] = qv.z; dst[6] = qv.w;
    }
    // stage K chunk, XOR-swizzled at float4 granularity
    int k0 = c * CK;
    for (int i = tid; i < CK * (Dd / 4); i += K3T) {
        int row = i >> 4, c4 = i & 15;
        ks4[row * 16 + (c4 ^ (row & 7))] =
            k4g[((size_t)(b * Ll + k0 + row) * Hh + h) * (Dd / 4) + c4];
    }
    __syncthreads();

    // S-phase: j = tid&255; lower half does u-pairs 0..11, upper 12..22
    {
        int j = tid & 255;
        if (tid < 256) s_pass<12>(0,  j, ks4, qsU, ss);
        else           s_pass<11>(12, j, ks4, qsU, ss);
    }
    __syncthreads();

    // partial softmax per row u (warp-per-row, 16 warps)
    int wid = tid >> 5, lane = tid & 31;
    for (int u = wid; u < SSK; u += 16) {
        float x[8];
        float mxv = -1e30f;
        #pragma unroll
        for (int t = 0; t < 8; t++) { x[t] = ss[u * SST + lane + t * 32]; mxv = fmaxf(mxv, x[t]); }
        #pragma unroll
        for (int o = 16; o; o >>= 1) mxv = fmaxf(mxv, __shfl_xor_sync(0xffffffffu, mxv, o));
        float sum = 0.f;
        #pragma unroll
        for (int t = 0; t < 8; t++) { float p = __expf(0.125f * (x[t] - mxv)); x[t] = p; sum += p; }
        #pragma unroll
        for (int o = 16; o; o >>= 1) sum += __shfl_xor_sync(0xffffffffu, sum, o);
        #pragma unroll
        for (int t = 0; t < 8; t++) ss[u * SST + lane + t * 32] = x[t];
        if (lane == 0) {
            g_pmax[(bh * NC + c) * SSK + u] = 0.125f * mxv;
            g_psum[(bh * NC + c) * SSK + u] = sum;
        }
    }
    __syncthreads();

    // stage V chunk into the K buffer (same swizzle)
    for (int i = tid; i < CK * (Dd / 4); i += K3T) {
        int row = i >> 4, c4 = i & 15;
        ks4[row * 16 + (c4 ^ (row & 7))] =
            v4g[((size_t)(b * Ll + k0 + row) * Hh + h) * (Dd / 4) + c4];
    }
    __syncthreads();

    // P@V: thread = (ug, d4); ug in [0,32) owns u = ug and (if <45) ug+32
    int d4 = tid & 15, ug = tid >> 4;
    ulonglong2* po = (ulonglong2*)g_pout;
    size_t baseo = ((size_t)(bh * NC + c) * SSK) * 16 + d4;
    #pragma unroll
    for (int p = 0; p < 2; p++) {
        int u = ug + p * 32;
        if (u < SSK) {
            ull al = 0, ah = 0;
            #pragma unroll 4
            for (int jj = 0; jj < CK; jj++) {
                ulonglong2 vv = ksU[jj * 16 + (d4 ^ (jj & 7))];
                float pw = ss[u * SST + jj];
                ull pb = pack2(pw, pw);
                al = fma2(pb, vv.x, al);
                ah = fma2(pb, vv.y, ah);
            }
            po[baseo + (size_t)u * 16] = make_ulonglong2(al, ah);
        }
    }
}

// ---------------- K4: combine partials + scatter ----------------
__global__ __launch_bounds__(256) void k4_combine(float4* __restrict__ out4) {
    int bh = blockIdx.x;
    int b = bh >> 3, h = bh & 7;
    for (int i = threadIdx.x; i < SSK * 16; i += 256) {
        int u = i >> 4, d4 = i & 15;
        float gm = -1e30f;
        #pragma unroll
        for (int cc = 0; cc < NC; cc++)
            gm = fmaxf(gm, g_pmax[(bh * NC + cc) * SSK + u]);
        float denom = 0.f;
        float4 a = make_float4(0.f, 0.f, 0.f, 0.f);
        #pragma unroll
        for (int cc = 0; cc < NC; cc++) {
            float w = __expf(g_pmax[(bh * NC + cc) * SSK + u] - gm);
            denom += g_psum[(bh * NC + cc) * SSK + u] * w;
            float4 po = g_pout[((bh * NC + cc) * SSK + u) * 16 + d4];
            a.x += w * po.x; a.y += w * po.y; a.z += w * po.z; a.w += w * po.w;
        }
        float inv = 1.0f / denom;
        a.x *= inv; a.y *= inv; a.z *= inv; a.w *= inv;
        int lsel = g_top[bh * SSK + u];
        out4[((size_t)(b * Ll + lsel) * Hh + h) * 16 + d4] = a;
    }
}

// ---------------- launch ----------------
extern "C" void kernel_launch(void* const* d_in, const int* in_sizes, int n_in,
                              void* d_out, int out_size) {
    const float4* q4 = (const float4*)d_in[0];
    const float4* k4 = (const float4*)d_in[1];
    const float4* v4 = (const float4*)d_in[2];
    const void* idxp = d_in[n_in - 1];
    for (int i = 0; i < n_in; i++)
        if (in_sizes[i] == Ll * SSK) idxp = d_in[i];
    float4* out4 = (float4*)d_out;

    cudaFuncSetAttribute(k3_attn, cudaFuncAttributeMaxDynamicSharedMemorySize, K3_SMEM);

    int n4 = out_size / 4;
    k0_zero<<<(n4 + 255) / 256, 256>>>(out4, n4, (const unsigned*)idxp);
    k1_score<<<Bb * Ll / 8, 256>>>(q4, k4, idxp);
    k2_topk<<<BH, 256>>>();
    k3_attn<<<dim3(NC, BH), K3T, K3_SMEM>>>(q4, k4, v4);
    k4_combine<<<BH, 256>>>(out4);
}

// round 9
// speedup vs baseline: 1.2319x; 1.2319x over previous
#include <cuda_runtime.h>

// ProbAttention (Informer ProbSparse) for B=2, L=4096, H=8, D=64, sample_k = n_top = 45.

#define Bb   2
#define Ll   4096
#define Hh   8
#define Dd   64
#define SSK  45          // sample_k == n_top
#define BH   (Bb*Hh)     // 16
#define NC   16          // kv chunks in phase 3
#define CK   256         // keys per chunk (NC*CK == Ll)
#define SST  257         // padded ss row stride (floats)

typedef unsigned long long ull;

// ---- scratch (static device globals: no allocation allowed) ----
__device__ int    g_idx_is64;
__device__ float  g_M[BH * Ll];
__device__ int    g_top[BH * SSK];
__device__ float  g_pmax[BH * NC * SSK];
__device__ float  g_psum[BH * NC * SSK];
__device__ float4 g_pout[BH * NC * SSK * (Dd / 4)];

// ---- f32x2 packed-FMA helpers ----
__device__ __forceinline__ ull fma2(ull a, ull b, ull c) {
    ull d;
    asm("fma.rn.f32x2 %0, %1, %2, %3;" : "=l"(d) : "l"(a), "l"(b), "l"(c));
    return d;
}
__device__ __forceinline__ ull pack2(float x, float y) {
    ull r;
    asm("mov.b64 %0, {%1, %2};" : "=l"(r) : "f"(x), "f"(y));
    return r;
}
__device__ __forceinline__ void unpack2(ull v, float& x, float& y) {
    asm("mov.b64 {%0, %1}, %2;" : "=f"(x), "=f"(y) : "l"(v));
}

// ---------------- K0: zero output + detect index dtype ----------------
__global__ void k0_zero(float4* __restrict__ out4, int n4,
                        const unsigned* __restrict__ idxsrc) {
    if (blockIdx.x == 0) {
        __shared__ int nz;
        if (threadIdx.x == 0) nz = 0;
        __syncthreads();
        if (threadIdx.x < 128) {
            unsigned v = idxsrc[threadIdx.x * 2 + 1];
            if (v != 0u) atomicAdd(&nz, 1);
        }
        __syncthreads();
        if (threadIdx.x == 0) g_idx_is64 = (nz == 0) ? 1 : 0;
    }
    int i = blockIdx.x * 256 + threadIdx.x;
    if (i < n4) out4[i] = make_float4(0.f, 0.f, 0.f, 0.f);
}

// ---------------- K1: sampled scores M ----------------
// One warp per (b,l); 8 heads at once; fully coalesced 512B loads per step.
__global__ __launch_bounds__(256) void k1_score(const float4* __restrict__ q4,
                                                const float4* __restrict__ k4,
                                                const void* __restrict__ idxsrc) {
    int w    = blockIdx.x * 8 + (threadIdx.x >> 5);
    int lane = threadIdx.x & 31;
    int b = w >> 12;
    int l = w & (Ll - 1);

    const float4* qp = q4 + (size_t)(b * Ll + l) * (Hh * Dd / 4);
    float4 qv[4];
    #pragma unroll
    for (int t = 0; t < 4; t++) qv[t] = qp[t * 32 + lane];

    float mx[4] = {-1e30f, -1e30f, -1e30f, -1e30f};
    float sm[4] = {0.f, 0.f, 0.f, 0.f};

    const int is64 = g_idx_is64;
    const long long* ip64 = (const long long*)idxsrc + (size_t)l * SSK;
    const int*       ip32 = (const int*)idxsrc + (size_t)l * SSK;

    #pragma unroll 2
    for (int s = 0; s < SSK; s++) {
        int idx = is64 ? (int)ip64[s] : ip32[s];
        const float4* kp = k4 + (size_t)(b * Ll + idx) * (Hh * Dd / 4);
        #pragma unroll
        for (int t = 0; t < 4; t++) {
            float4 kv = kp[t * 32 + lane];
            float p = qv[t].x*kv.x + qv[t].y*kv.y + qv[t].z*kv.z + qv[t].w*kv.w;
            p += __shfl_xor_sync(0xffffffffu, p, 8);
            p += __shfl_xor_sync(0xffffffffu, p, 4);
            p += __shfl_xor_sync(0xffffffffu, p, 2);
            p += __shfl_xor_sync(0xffffffffu, p, 1);
            mx[t] = fmaxf(mx[t], p);
            sm[t] += p;
        }
    }
    if ((lane & 15) == 0) {
        int half = lane >> 4;
        #pragma unroll
        for (int t = 0; t < 4; t++) {
            int h = 2 * t + half;
            g_M[(b * Hh + h) * Ll + l] = mx[t] - sm[t] * (1.0f / (float)Ll);
        }
    }
}

// ---------------- K2: top-45 per (b,h) via 4-round radix select ----------------
__global__ __launch_bounds__(256) void k2_topk() {
    int bh  = blockIdx.x;
    int tid = threadIdx.x;
    int wid = tid >> 5, lane = tid & 31;

    __shared__ unsigned hist[256];
    __shared__ unsigned warptot[8];
    __shared__ unsigned sh_pivot, sh_above;
    __shared__ int n_gt, n_eq;

    unsigned key[16];
    #pragma unroll
    for (int i = 0; i < 16; i++) {
        unsigned u = __float_as_uint(g_M[bh * Ll + i * 256 + tid]);
        key[i] = (u & 0x80000000u) ? ~u : (u | 0x80000000u);
    }

    unsigned prefix = 0, pmask = 0;
    int need = SSK;

    #pragma unroll
    for (int round = 0; round < 4; round++) {
        int shift = 24 - round * 8;
        hist[tid] = 0;
        if (tid == 0) { n_gt = 0; n_eq = 0; }
        __syncthreads();
        #pragma unroll
        for (int i = 0; i < 16; i++)
            if ((key[i] & pmask) == prefix)
                atomicAdd(&hist[(key[i] >> shift) & 255u], 1u);
        __syncthreads();

        unsigned x = hist[tid];
        unsigned s = x;
        #pragma unroll
        for (int o = 1; o < 32; o <<= 1) {
            unsigned y = __shfl_down_sync(0xffffffffu, s, o);
            if (lane + o < 32) s += y;
        }
        unsigned wt = __shfl_sync(0xffffffffu, s, 0);
        if (lane == 0) warptot[wid] = wt;
        __syncthreads();
        unsigned hs = 0;
        #pragma unroll
        for (int w2 = 0; w2 < 8; w2++)
            if (w2 > wid) hs += warptot[w2];
        unsigned S = s + hs;
        unsigned above = S - x;
        if ((int)S >= need && (int)above < need) {
            sh_pivot = (unsigned)tid;
            sh_above = above;
        }
        __syncthreads();
        prefix |= sh_pivot << shift;
        pmask  |= 0xffu << shift;
        need   -= (int)sh_above;
        __syncthreads();
    }

    int base = bh * SSK;
    #pragma unroll
    for (int i = 0; i < 16; i++)
        if (key[i] > prefix) {
            int p = atomicAdd(&n_gt, 1);
            g_top[base + p] = i * 256 + tid;
        }
    __syncthreads();
    int gt = n_gt;
    #pragma unroll
    for (int i = 0; i < 16; i++)
        if (key[i] == prefix) {
            int e = atomicAdd(&n_eq, 1);
            if (e < need) g_top[base + gt + e] = i * 256 + tid;
        }
}

// ---------------- K3: split-KV sparse attention partials ----------------
// 256 threads. Smem cut to ~95KB (K staged in two 32-dim chunks, V in two
// 128-key chunks, padded strides instead of XOR swizzle) -> 2 CTAs/SM,
// 256 CTAs in one resident wave; barrier stalls overlapped across CTAs.
#define K3T   256
#define QS2F  (23 * 128)
#define KVF   (CK * 9 * 4)          // 9216 floats: K chunk 256x9 float4 (V: 128x17 fits)
#define K3_SMEM ((QS2F + KVF + SSK * SST) * 4 + 256)

__global__ __launch_bounds__(K3T, 2) void k3_attn(const float4* __restrict__ q4,
                                                  const float4* __restrict__ k4g,
                                                  const float4* __restrict__ v4g) {
    int c  = blockIdx.x;
    int bh = blockIdx.y;
    int b = bh >> 3, h = bh & 7;
    int tid = threadIdx.x;

    extern __shared__ float smem[];
    float* qs2f = smem;                   // 23*128 floats (u-pair packed Q)
    float* kv   = qs2f + QS2F;            // 9216 floats (K d-chunk / V key-chunk)
    float* ss   = kv + KVF;               // 45*257 floats
    int*   tops = (int*)(ss + SSK * SST);
    float4*           kv4 = (float4*)kv;
    const ulonglong2* kvU = (const ulonglong2*)kv;
    const ulonglong2* qsU = (const ulonglong2*)qs2f;

    if (tid < SSK) tops[tid] = g_top[bh * SSK + tid];
    __syncthreads();

    // stage Q in u-pair-packed layout: qs2f[(u>>1)*128 + 8*c4 + 2*(comp) + (u&1)]
    for (int i = tid; i < 46 * 16; i += K3T) {
        int u = i >> 4, c4 = i & 15;
        float4 qv = (u < SSK)
            ? q4[((size_t)(b * Ll + tops[u]) * Hh + h) * (Dd / 4) + c4]
            : make_float4(0.f, 0.f, 0.f, 0.f);
        float* dst = qs2f + ((u >> 1) * 128 + 8 * c4) + (u & 1);
        dst[0] = qv.x; dst[2] = qv.y; dst[4] = qv.z; dst[6] = qv.w;
    }

    int k0 = c * CK;
    int j = tid;

    // S-phase: acc for 23 u-pairs in registers, K staged in two 32-dim chunks
    ull acc[23];
    #pragma unroll
    for (int i = 0; i < 23; i++) acc[i] = 0ull;

    #pragma unroll 1
    for (int cc = 0; cc < 2; cc++) {
        __syncthreads();   // buffer reuse guard (also covers Q staging, cc=0)
        for (int i = tid; i < CK * 8; i += K3T) {
            int row = i >> 3, dc = i & 7;
            kv4[row * 9 + dc] =
                k4g[((size_t)(b * Ll + k0 + row) * Hh + h) * 16 + cc * 8 + dc];
        }
        __syncthreads();
        #pragma unroll 1
        for (int dc = 0; dc < 8; dc++) {
            float4 kr = kv4[j * 9 + dc];
            ull kk0 = pack2(kr.x, kr.x);
            ull kk1 = pack2(kr.y, kr.y);
            ull kk2 = pack2(kr.z, kr.z);
            ull kk3 = pack2(kr.w, kr.w);
            int dcg = cc * 8 + dc;
            #pragma unroll
            for (int i = 0; i < 23; i++) {
                ulonglong2 qA = qsU[i * 32 + dcg * 2];      // d = 4dcg, 4dcg+1
                ulonglong2 qB = qsU[i * 32 + dcg * 2 + 1];  // d = 4dcg+2, 4dcg+3
                acc[i] = fma2(qA.x, kk0, acc[i]);
                acc[i] = fma2(qA.y, kk1, acc[i]);
                acc[i] = fma2(qB.x, kk2, acc[i]);
                acc[i] = fma2(qB.y, kk3, acc[i]);
            }
        }
    }
    #pragma unroll
    for (int i = 0; i < 23; i++) {
        float lo, hi;
        unpack2(acc[i], lo, hi);
        ss[(2 * i) * SST + j] = lo;
        if (2 * i + 1 < SSK) ss[(2 * i + 1) * SST + j] = hi;
    }
    __syncthreads();

    // partial softmax per row u (warp-per-row, 8 warps)
    int wid = tid >> 5, lane = tid & 31;
    for (int u = wid; u < SSK; u += 8) {
        float x[8];
        float mxv = -1e30f;
        #pragma unroll
        for (int t = 0; t < 8; t++) { x[t] = ss[u * SST + lane + t * 32]; mxv = fmaxf(mxv, x[t]); }
        #pragma unroll
        for (int o = 16; o; o >>= 1) mxv = fmaxf(mxv, __shfl_xor_sync(0xffffffffu, mxv, o));
        float sum = 0.f;
        #pragma unroll
        for (int t = 0; t < 8; t++) { float p = __expf(0.125f * (x[t] - mxv)); x[t] = p; sum += p; }
        #pragma unroll
        for (int o = 16; o; o >>= 1) sum += __shfl_xor_sync(0xffffffffu, sum, o);
        #pragma unroll
        for (int t = 0; t < 8; t++) ss[u * SST + lane + t * 32] = x[t];
        if (lane == 0) {
            g_pmax[(bh * NC + c) * SSK + u] = 0.125f * mxv;
            g_psum[(bh * NC + c) * SSK + u] = sum;
        }
    }

    // P@V: V staged in two 128-key chunks; thread = (ug, d4), ug<15 owns 3 u's
    int d4 = tid & 15, ug = tid >> 4;
    int u0 = ug * 3;
    ull a0l = 0, a0h = 0, a1l = 0, a1h = 0, a2l = 0, a2h = 0;

    #pragma unroll 1
    for (int vc = 0; vc < 2; vc++) {
        __syncthreads();   // vc=0: softmax done; vc=1: PV pass 0 done
        for (int i = tid; i < 128 * 16; i += K3T) {
            int row = i >> 4, c4 = i & 15;
            kv4[row * 17 + c4] =
                v4g[((size_t)(b * Ll + k0 + vc * 128 + row) * Hh + h) * 16 + c4];
        }
        __syncthreads();
        if (ug < 15) {
            #pragma unroll 4
            for (int jj = 0; jj < 128; jj++) {
                ulonglong2 vv = kvU[jj * 17 + d4];
                int jg = vc * 128 + jj;
                float p0 = ss[u0 * SST + jg];
                float p1 = ss[(u0 + 1) * SST + jg];
                float p2 = ss[(u0 + 2) * SST + jg];
                ull b0 = pack2(p0, p0), b1 = pack2(p1, p1), b2 = pack2(p2, p2);
                a0l = fma2(b0, vv.x, a0l);  a0h = fma2(b0, vv.y, a0h);
                a1l = fma2(b1, vv.x, a1l);  a1h = fma2(b1, vv.y, a1h);
                a2l = fma2(b2, vv.x, a2l);  a2h = fma2(b2, vv.y, a2h);
            }
        }
    }
    if (ug < 15) {
        ulonglong2* po = (ulonglong2*)g_pout;
        size_t baseo = ((size_t)(bh * NC + c) * SSK) * 16 + d4;
        po[baseo + (size_t)u0 * 16]       = make_ulonglong2(a0l, a0h);
        po[baseo + (size_t)(u0 + 1) * 16] = make_ulonglong2(a1l, a1h);
        po[baseo + (size_t)(u0 + 2) * 16] = make_ulonglong2(a2l, a2h);
    }
}

// ---------------- K4: combine partials + scatter ----------------
__global__ __launch_bounds__(256) void k4_combine(float4* __restrict__ out4) {
    int bh = blockIdx.x;
    int b = bh >> 3, h = bh & 7;
    for (int i = threadIdx.x; i < SSK * 16; i += 256) {
        int u = i >> 4, d4 = i & 15;
        float gm = -1e30f;
        #pragma unroll
        for (int cc = 0; cc < NC; cc++)
            gm = fmaxf(gm, g_pmax[(bh * NC + cc) * SSK + u]);
        float denom = 0.f;
        float4 a = make_float4(0.f, 0.f, 0.f, 0.f);
        #pragma unroll
        for (int cc = 0; cc < NC; cc++) {
            float w = __expf(g_pmax[(bh * NC + cc) * SSK + u] - gm);
            denom += g_psum[(bh * NC + cc) * SSK + u] * w;
            float4 po = g_pout[((bh * NC + cc) * SSK + u) * 16 + d4];
            a.x += w * po.x; a.y += w * po.y; a.z += w * po.z; a.w += w * po.w;
        }
        float inv = 1.0f / denom;
        a.x *= inv; a.y *= inv; a.z *= inv; a.w *= inv;
        int lsel = g_top[bh * SSK + u];
        out4[((size_t)(b * Ll + lsel) * Hh + h) * 16 + d4] = a;
    }
}

// ---------------- launch ----------------
extern "C" void kernel_launch(void* const* d_in, const int* in_sizes, int n_in,
                              void* d_out, int out_size) {
    const float4* q4 = (const float4*)d_in[0];
    const float4* k4 = (const float4*)d_in[1];
    const float4* v4 = (const float4*)d_in[2];
    const void* idxp = d_in[n_in - 1];
    for (int i = 0; i < n_in; i++)
        if (in_sizes[i] == Ll * SSK) idxp = d_in[i];
    float4* out4 = (float4*)d_out;

    cudaFuncSetAttribute(k3_attn, cudaFuncAttributeMaxDynamicSharedMemorySize, K3_SMEM);

    int n4 = out_size / 4;
    k0_zero<<<(n4 + 255) / 256, 256>>>(out4, n4, (const unsigned*)idxp);
    k1_score<<<Bb * Ll / 8, 256>>>(q4, k4, idxp);
    k2_topk<<<BH, 256>>>();
    k3_attn<<<dim3(NC, BH), K3T, K3_SMEM>>>(q4, k4, v4);
    k4_combine<<<BH, 256>>>(out4);
}